// round 3
// baseline (speedup 1.0000x reference)
#include <cuda_runtime.h>

// Problem constants
#define NB   8
#define TT   2048
#define CC   512
#define MTOT (NB*TT)        // 16384
#define NEG_INF __int_as_float(0xff800000)

// Scratch (device globals -- no runtime allocation allowed)
__device__ float g_q[MTOT*CC];
__device__ float g_k[MTOT*CC];
__device__ float g_v[MTOT*CC];
__device__ float g_s[(size_t)NB*TT*TT];

// ---------------------------------------------------------------------------
// Shared 128x128x8 register-blocked GEMM core:
// 256 threads, each owns an 8x8 micro-tile split into 2x2 groups of 4
// (rows {ty*4, 64+ty*4}, cols {tx*4, 64+tx*4}) for conflict-light smem reads.
// ---------------------------------------------------------------------------
#define GEMM_INNER(As, Bs, acc, tx, ty)                                      \
    _Pragma("unroll")                                                        \
    for (int kk = 0; kk < 8; kk++) {                                         \
        const float4 a0 = *(const float4*)&As[kk][(ty)*4];                   \
        const float4 a1 = *(const float4*)&As[kk][64 + (ty)*4];              \
        const float4 b0 = *(const float4*)&Bs[kk][(tx)*4];                   \
        const float4 b1 = *(const float4*)&Bs[kk][64 + (tx)*4];              \
        const float av[8] = {a0.x,a0.y,a0.z,a0.w,a1.x,a1.y,a1.z,a1.w};       \
        const float bv[8] = {b0.x,b0.y,b0.z,b0.w,b1.x,b1.y,b1.z,b1.w};       \
        _Pragma("unroll")                                                    \
        for (int i = 0; i < 8; i++)                                          \
            _Pragma("unroll")                                                \
            for (int j = 0; j < 8; j++)                                      \
                acc[i][j] = fmaf(av[i], bv[j], acc[i][j]);                   \
    }

// ---------------------------------------------------------------------------
// Kernel 1: QKV projection.  out[M,512] = X[M,512] @ W[512,512] + bias
// which: 0->g_q, 1->g_k, 2->g_v
// ---------------------------------------------------------------------------
__global__ __launch_bounds__(256) void proj_kernel(
    const float* __restrict__ X, const float* __restrict__ W,
    const float* __restrict__ bias, int which)
{
    float* out = (which == 0) ? g_q : ((which == 1) ? g_k : g_v);
    const int m0 = blockIdx.y * 128;
    const int n0 = blockIdx.x * 128;

    __shared__ float As[8][132];
    __shared__ float Bs[8][132];

    const int tid = threadIdx.x;
    const int tx = tid & 15, ty = tid >> 4;
    const int ar = tid >> 1, ac = (tid & 1) * 4;     // A loader: row, k-offset
    const int br = tid >> 5, bc = (tid & 31) * 4;    // B loader: k-row, col

    float acc[8][8];
    #pragma unroll
    for (int i = 0; i < 8; i++)
        #pragma unroll
        for (int j = 0; j < 8; j++) acc[i][j] = 0.f;

    for (int k0 = 0; k0 < 512; k0 += 8) {
        const float4 avld = *(const float4*)&X[(size_t)(m0 + ar) * 512 + k0 + ac];
        As[ac + 0][ar] = avld.x; As[ac + 1][ar] = avld.y;
        As[ac + 2][ar] = avld.z; As[ac + 3][ar] = avld.w;
        *(float4*)&Bs[br][bc] = *(const float4*)&W[(size_t)(k0 + br) * 512 + n0 + bc];
        __syncthreads();
        GEMM_INNER(As, Bs, acc, tx, ty);
        __syncthreads();
    }

    float bvals[8];
    #pragma unroll
    for (int j = 0; j < 8; j++) {
        const int cl = (j < 4) ? (tx * 4 + j) : (64 + tx * 4 + (j - 4));
        bvals[j] = bias[n0 + cl];
    }
    #pragma unroll
    for (int i = 0; i < 8; i++) {
        const int rl = (i < 4) ? (ty * 4 + i) : (64 + ty * 4 + (i - 4));
        const size_t rbase = (size_t)(m0 + rl) * 512 + n0;
        float4 o0 = make_float4(acc[i][0] + bvals[0], acc[i][1] + bvals[1],
                                acc[i][2] + bvals[2], acc[i][3] + bvals[3]);
        float4 o1 = make_float4(acc[i][4] + bvals[4], acc[i][5] + bvals[5],
                                acc[i][6] + bvals[6], acc[i][7] + bvals[7]);
        *(float4*)&out[rbase + tx * 4]      = o0;
        *(float4*)&out[rbase + 64 + tx * 4] = o1;
    }
}

// ---------------------------------------------------------------------------
// Kernel 2: copy x into first 512 output channels (float4 vectorized)
// ---------------------------------------------------------------------------
__global__ __launch_bounds__(256) void copy_x_kernel(
    const float4* __restrict__ x4, float4* __restrict__ out4)
{
    const int gid = blockIdx.x * 256 + threadIdx.x;  // MTOT*128 elements
    const int bt = gid >> 7, c4 = gid & 127;
    out4[(size_t)bt * 256 + c4] = x4[gid];
}

// ---------------------------------------------------------------------------
// Kernel 3: scores  S[b,i,j] = (q_i . k_j) / sqrt(512), causal (-inf above diag)
// Only lower-triangle tiles are computed.
// ---------------------------------------------------------------------------
__global__ __launch_bounds__(256) void score_kernel()
{
    const int jt = blockIdx.x, it = blockIdx.y, b = blockIdx.z;
    if (jt > it) return;

    const float* q = g_q + (size_t)b * TT * CC;
    const float* k = g_k + (size_t)b * TT * CC;
    float*       S = g_s + (size_t)b * TT * TT;
    const int i0 = it * 128, j0 = jt * 128;

    __shared__ float As[8][132];
    __shared__ float Bs[8][132];

    const int tid = threadIdx.x;
    const int tx = tid & 15, ty = tid >> 4;
    const int ar = tid >> 1, ac = (tid & 1) * 4;
    const int ccb = tid & 7;            // B loader: k-offset within BK
    const int jb  = tid >> 3;           // B loader: base col (0..31), 4 iters

    float acc[8][8];
    #pragma unroll
    for (int i = 0; i < 8; i++)
        #pragma unroll
        for (int j = 0; j < 8; j++) acc[i][j] = 0.f;

    for (int k0 = 0; k0 < 512; k0 += 8) {
        const float4 avld = *(const float4*)&q[(size_t)(i0 + ar) * 512 + k0 + ac];
        As[ac + 0][ar] = avld.x; As[ac + 1][ar] = avld.y;
        As[ac + 2][ar] = avld.z; As[ac + 3][ar] = avld.w;
        #pragma unroll
        for (int it4 = 0; it4 < 4; it4++) {
            const int jj = it4 * 32 + jb;
            Bs[ccb][jj] = k[(size_t)(j0 + jj) * 512 + k0 + ccb];
        }
        __syncthreads();
        GEMM_INNER(As, Bs, acc, tx, ty);
        __syncthreads();
    }

    const float scale = 0.044194173824159216f;  // 1/sqrt(512)
    const bool diag = (it == jt);
    #pragma unroll
    for (int i = 0; i < 8; i++) {
        const int rl = (i < 4) ? (ty * 4 + i) : (64 + ty * 4 + (i - 4));
        const int ig = i0 + rl;
        #pragma unroll
        for (int g = 0; g < 2; g++) {
            const int jg = j0 + g * 64 + tx * 4;
            float4 o;
            o.x = (diag && jg + 0 > ig) ? NEG_INF : acc[i][g * 4 + 0] * scale;
            o.y = (diag && jg + 1 > ig) ? NEG_INF : acc[i][g * 4 + 1] * scale;
            o.z = (diag && jg + 2 > ig) ? NEG_INF : acc[i][g * 4 + 2] * scale;
            o.w = (diag && jg + 3 > ig) ? NEG_INF : acc[i][g * 4 + 3] * scale;
            *(float4*)&S[(size_t)ig * TT + jg] = o;
        }
    }
}

// ---------------------------------------------------------------------------
// Kernel 4: row softmax (in place).  Row i has valid j in [0, i]; entries up to
// the 128-boundary L were written (-inf above diag) -> exp gives exact zeros.
// ---------------------------------------------------------------------------
__global__ __launch_bounds__(256) void softmax_kernel()
{
    const int i = blockIdx.x, b = blockIdx.y;
    float* S = g_s + (size_t)b * TT * TT + (size_t)i * TT;
    const int L = ((i >> 7) + 1) << 7;   // ceil(i+1, 128)
    const int tid = threadIdx.x;

    float e[8];
    float m = NEG_INF;
    int n = 0;
    for (int j = tid; j < L; j += 256) { const float s = S[j]; e[n++] = s; m = fmaxf(m, s); }

    __shared__ float red[256];
    red[tid] = m; __syncthreads();
    #pragma unroll
    for (int s = 128; s > 0; s >>= 1) {
        if (tid < s) red[tid] = fmaxf(red[tid], red[tid + s]);
        __syncthreads();
    }
    m = red[0]; __syncthreads();

    float sum = 0.f;
    for (int t = 0; t < n; t++) { e[t] = expf(e[t] - m); sum += e[t]; }
    red[tid] = sum; __syncthreads();
    #pragma unroll
    for (int s = 128; s > 0; s >>= 1) {
        if (tid < s) red[tid] += red[tid + s];
        __syncthreads();
    }
    const float inv = 1.0f / red[0];

    int t = 0;
    for (int j = tid; j < L; j += 256) S[j] = e[t++] * inv;
}

// ---------------------------------------------------------------------------
// Kernel 5: O = P @ V, K-extent bounded by causal row tile; writes channels
// [512,1024) of the output.
// ---------------------------------------------------------------------------
__global__ __launch_bounds__(256) void av_kernel(float* __restrict__ out)
{
    const int nt = blockIdx.x, it = blockIdx.y, b = blockIdx.z;
    const float* P = g_s + (size_t)b * TT * TT;
    const float* v = g_v + (size_t)b * TT * CC;
    const int i0 = it * 128, n0 = nt * 128;
    const int Kext = (it + 1) * 128;

    __shared__ float As[8][132];
    __shared__ float Bs[8][132];

    const int tid = threadIdx.x;
    const int tx = tid & 15, ty = tid >> 4;
    const int ar = tid >> 1, ac = (tid & 1) * 4;
    const int br = tid >> 5, bc = (tid & 31) * 4;

    float acc[8][8];
    #pragma unroll
    for (int i = 0; i < 8; i++)
        #pragma unroll
        for (int j = 0; j < 8; j++) acc[i][j] = 0.f;

    for (int k0 = 0; k0 < Kext; k0 += 8) {
        const float4 avld = *(const float4*)&P[(size_t)(i0 + ar) * TT + k0 + ac];
        As[ac + 0][ar] = avld.x; As[ac + 1][ar] = avld.y;
        As[ac + 2][ar] = avld.z; As[ac + 3][ar] = avld.w;
        *(float4*)&Bs[br][bc] = *(const float4*)&v[(size_t)(k0 + br) * 512 + n0 + bc];
        __syncthreads();
        GEMM_INNER(As, Bs, acc, tx, ty);
        __syncthreads();
    }

    #pragma unroll
    for (int i = 0; i < 8; i++) {
        const int rl = (i < 4) ? (ty * 4 + i) : (64 + ty * 4 + (i - 4));
        const size_t rbase = ((size_t)b * TT + (i0 + rl)) * 1024 + 512 + n0;
        float4 o0 = make_float4(acc[i][0], acc[i][1], acc[i][2], acc[i][3]);
        float4 o1 = make_float4(acc[i][4], acc[i][5], acc[i][6], acc[i][7]);
        *(float4*)&out[rbase + tx * 4]      = o0;
        *(float4*)&out[rbase + 64 + tx * 4] = o1;
    }
}

// ---------------------------------------------------------------------------
extern "C" void kernel_launch(void* const* d_in, const int* in_sizes, int n_in,
                              void* d_out, int out_size)
{
    const float* x  = (const float*)d_in[0];
    const float* Wq = (const float*)d_in[1];
    const float* bq = (const float*)d_in[2];
    const float* Wk = (const float*)d_in[3];
    const float* bk = (const float*)d_in[4];
    const float* Wv = (const float*)d_in[5];
    const float* bv = (const float*)d_in[6];
    float* out = (float*)d_out;

    const dim3 gProj(4, 128);              // N tiles x M tiles
    proj_kernel<<<gProj, 256>>>(x, Wq, bq, 0);
    proj_kernel<<<gProj, 256>>>(x, Wk, bk, 1);
    proj_kernel<<<gProj, 256>>>(x, Wv, bv, 2);

    copy_x_kernel<<<(MTOT * 128) / 256, 256>>>((const float4*)x, (float4*)out);

    score_kernel<<<dim3(16, 16, NB), 256>>>();
    softmax_kernel<<<dim3(TT, NB), 256>>>();
    av_kernel<<<dim3(4, 16, NB), 256>>>(out);
}

// round 4
// speedup vs baseline: 1.8998x; 1.8998x over previous
#include <cuda_runtime.h>

// Problem constants
#define NB   8
#define TT   2048
#define CC   512
#define MTOT (NB*TT)        // 16384
#define NEG_INF __int_as_float(0xff800000)

// Scratch (device globals -- no runtime allocation allowed)
__device__ float g_q[MTOT*CC];
__device__ float g_k[MTOT*CC];
__device__ float g_v[MTOT*CC];
__device__ float g_s[(size_t)NB*TT*TT];

// ---------------------------------------------------------------------------
// tf32 helpers
// ---------------------------------------------------------------------------
__device__ __forceinline__ unsigned f2tf(float f) {
    unsigned u; asm("cvt.rna.tf32.f32 %0, %1;" : "=r"(u) : "f"(f)); return u;
}
__device__ __forceinline__ uint4 f4tf(float4 v) {
    return make_uint4(f2tf(v.x), f2tf(v.y), f2tf(v.z), f2tf(v.w));
}
__device__ __forceinline__ void mma8(float* c, const unsigned* a, const unsigned* b) {
    asm volatile(
        "mma.sync.aligned.m16n8k8.row.col.f32.tf32.tf32.f32 "
        "{%0,%1,%2,%3}, {%4,%5,%6,%7}, {%8,%9}, {%0,%1,%2,%3};\n"
        : "+f"(c[0]), "+f"(c[1]), "+f"(c[2]), "+f"(c[3])
        : "r"(a[0]), "r"(a[1]), "r"(a[2]), "r"(a[3]), "r"(b[0]), "r"(b[1]));
}

// ---------------------------------------------------------------------------
// Tiling: CTA = 128x128, BK = 16. 8 warps in a 4(m) x 2(n) grid; each warp
// owns 32x64 = 2 m-frags (16) x 8 n-frags (8). Fragments per PTX m16n8k8
// layout (gid = lane>>2, tig = lane&3).
// As[128][20] (pitch 20: conflict-free A-frag LDS), Bs[16][132] (pitch 132:
// conflict-free B-frag LDS).
// ---------------------------------------------------------------------------
#define MMA_TILE()                                                            \
    _Pragma("unroll")                                                         \
    for (int ks = 0; ks < 2; ks++) {                                          \
        const int kk = ks * 8;                                                \
        unsigned af[2][4], bf[8][2];                                          \
        _Pragma("unroll")                                                     \
        for (int mf = 0; mf < 2; mf++) {                                      \
            const int r = wm * 32 + mf * 16 + gid;                            \
            af[mf][0] = As[r][kk + tig];                                      \
            af[mf][1] = As[r + 8][kk + tig];                                  \
            af[mf][2] = As[r][kk + tig + 4];                                  \
            af[mf][3] = As[r + 8][kk + tig + 4];                              \
        }                                                                     \
        _Pragma("unroll")                                                     \
        for (int nf = 0; nf < 8; nf++) {                                      \
            const int cb = wn * 64 + nf * 8 + gid;                            \
            bf[nf][0] = Bs[kk + tig][cb];                                     \
            bf[nf][1] = Bs[kk + tig + 4][cb];                                 \
        }                                                                     \
        _Pragma("unroll")                                                     \
        for (int mf = 0; mf < 2; mf++)                                        \
            _Pragma("unroll")                                                 \
            for (int nf = 0; nf < 8; nf++)                                    \
                mma8(acc[mf][nf], af[mf], bf[nf]);                            \
    }

#define DECL_TILE_STATE()                                                     \
    __shared__ unsigned As[128][20];                                          \
    __shared__ unsigned Bs[16][132];                                          \
    const int tid = threadIdx.x;                                              \
    const int wid = tid >> 5, lane = tid & 31;                                \
    const int wm = wid & 3, wn = wid >> 2;                                    \
    const int gid = lane >> 2, tig = lane & 3;                                \
    float acc[2][8][4];                                                       \
    _Pragma("unroll")                                                         \
    for (int mf = 0; mf < 2; mf++)                                            \
        _Pragma("unroll")                                                     \
        for (int nf = 0; nf < 8; nf++)                                        \
            _Pragma("unroll")                                                 \
            for (int q = 0; q < 4; q++) acc[mf][nf][q] = 0.f;

// ---------------------------------------------------------------------------
// Kernel 1: QKV projection.  out[M,512] = X[M,512] @ W[512,512] + bias
// blockIdx.z selects which projection (0=Q, 1=K, 2=V).
// ---------------------------------------------------------------------------
__global__ __launch_bounds__(256) void proj_kernel(
    const float* __restrict__ X,
    const float* __restrict__ Wq, const float* __restrict__ bq,
    const float* __restrict__ Wk, const float* __restrict__ bk,
    const float* __restrict__ Wv, const float* __restrict__ bv)
{
    const int which = blockIdx.z;
    const float* W    = (which == 0) ? Wq : (which == 1) ? Wk : Wv;
    const float* bias = (which == 0) ? bq : (which == 1) ? bk : bv;
    float* out        = (which == 0) ? g_q : (which == 1) ? g_k : g_v;

    const int m0 = blockIdx.y * 128;
    const int n0 = blockIdx.x * 128;

    DECL_TILE_STATE();

    const int lrA = tid >> 1, lkA = (tid & 1) * 8;     // A: row, k-offset
    const int lrB = tid >> 4, lnB = (tid & 15) * 8;    // B: k-row, col

    for (int k0 = 0; k0 < 512; k0 += 16) {
        const size_t abase = (size_t)(m0 + lrA) * 512 + k0 + lkA;
        *(uint4*)&As[lrA][lkA]     = f4tf(*(const float4*)&X[abase]);
        *(uint4*)&As[lrA][lkA + 4] = f4tf(*(const float4*)&X[abase + 4]);
        const size_t bbase = (size_t)(k0 + lrB) * 512 + n0 + lnB;
        *(uint4*)&Bs[lrB][lnB]     = f4tf(*(const float4*)&W[bbase]);
        *(uint4*)&Bs[lrB][lnB + 4] = f4tf(*(const float4*)&W[bbase + 4]);
        __syncthreads();
        MMA_TILE();
        __syncthreads();
    }

    #pragma unroll
    for (int mf = 0; mf < 2; mf++) {
        const int row = m0 + wm * 32 + mf * 16 + gid;
        #pragma unroll
        for (int nf = 0; nf < 8; nf++) {
            const int col = n0 + wn * 64 + nf * 8 + tig * 2;
            const float b0 = bias[col], b1 = bias[col + 1];
            float2 o0 = make_float2(acc[mf][nf][0] + b0, acc[mf][nf][1] + b1);
            float2 o1 = make_float2(acc[mf][nf][2] + b0, acc[mf][nf][3] + b1);
            *(float2*)&out[(size_t)row * 512 + col]       = o0;
            *(float2*)&out[(size_t)(row + 8) * 512 + col] = o1;
        }
    }
}

// ---------------------------------------------------------------------------
// Kernel 2: copy x into first 512 output channels (float4 vectorized)
// ---------------------------------------------------------------------------
__global__ __launch_bounds__(256) void copy_x_kernel(
    const float4* __restrict__ x4, float4* __restrict__ out4)
{
    const int gid = blockIdx.x * 256 + threadIdx.x;  // MTOT*128 elements
    const int bt = gid >> 7, c4 = gid & 127;
    out4[(size_t)bt * 256 + c4] = x4[gid];
}

// ---------------------------------------------------------------------------
// Kernel 3: scores  S[b,i,j] = (q_i . k_j) / sqrt(512), causal.
// Only lower-triangle tiles computed. K rows transposed into Bs[k][j].
// ---------------------------------------------------------------------------
__global__ __launch_bounds__(256) void score_kernel()
{
    const int jt = blockIdx.x, it = blockIdx.y, b = blockIdx.z;
    if (jt > it) return;

    const float* q = g_q + (size_t)b * TT * CC;
    const float* k = g_k + (size_t)b * TT * CC;
    float*       S = g_s + (size_t)b * TT * TT;
    const int i0 = it * 128, j0 = jt * 128;

    DECL_TILE_STATE();

    const int lrA = tid >> 1, lkA = (tid & 1) * 8;     // A (q): row, k-offset
    const int ljB = tid >> 1, lkB = (tid & 1) * 8;     // B (k): j-row, k-offset

    for (int k0 = 0; k0 < 512; k0 += 16) {
        const size_t abase = (size_t)(i0 + lrA) * 512 + k0 + lkA;
        *(uint4*)&As[lrA][lkA]     = f4tf(*(const float4*)&q[abase]);
        *(uint4*)&As[lrA][lkA + 4] = f4tf(*(const float4*)&q[abase + 4]);
        const size_t kbase = (size_t)(j0 + ljB) * 512 + k0 + lkB;
        const float4 kv0 = *(const float4*)&k[kbase];
        const float4 kv1 = *(const float4*)&k[kbase + 4];
        Bs[lkB + 0][ljB] = f2tf(kv0.x);
        Bs[lkB + 1][ljB] = f2tf(kv0.y);
        Bs[lkB + 2][ljB] = f2tf(kv0.z);
        Bs[lkB + 3][ljB] = f2tf(kv0.w);
        Bs[lkB + 4][ljB] = f2tf(kv1.x);
        Bs[lkB + 5][ljB] = f2tf(kv1.y);
        Bs[lkB + 6][ljB] = f2tf(kv1.z);
        Bs[lkB + 7][ljB] = f2tf(kv1.w);
        __syncthreads();
        MMA_TILE();
        __syncthreads();
    }

    const float scale = 0.044194173824159216f;  // 1/sqrt(512)
    const bool diag = (it == jt);
    #pragma unroll
    for (int mf = 0; mf < 2; mf++) {
        const int row = i0 + wm * 32 + mf * 16 + gid;
        #pragma unroll
        for (int nf = 0; nf < 8; nf++) {
            const int col = j0 + wn * 64 + nf * 8 + tig * 2;
            float2 o0 = make_float2(acc[mf][nf][0] * scale, acc[mf][nf][1] * scale);
            float2 o1 = make_float2(acc[mf][nf][2] * scale, acc[mf][nf][3] * scale);
            if (diag) {
                if (col     > row)     o0.x = NEG_INF;
                if (col + 1 > row)     o0.y = NEG_INF;
                if (col     > row + 8) o1.x = NEG_INF;
                if (col + 1 > row + 8) o1.y = NEG_INF;
            }
            *(float2*)&S[(size_t)row * TT + col]       = o0;
            *(float2*)&S[(size_t)(row + 8) * TT + col] = o1;
        }
    }
}

// ---------------------------------------------------------------------------
// Kernel 4: row softmax (in place), valid length rounded to 128.
// ---------------------------------------------------------------------------
__global__ __launch_bounds__(256) void softmax_kernel()
{
    const int i = blockIdx.x, b = blockIdx.y;
    float* S = g_s + (size_t)b * TT * TT + (size_t)i * TT;
    const int L = ((i >> 7) + 1) << 7;   // ceil(i+1, 128)
    const int tid = threadIdx.x;

    float e[8];
    float m = NEG_INF;
    int n = 0;
    for (int j = tid; j < L; j += 256) { const float s = S[j]; e[n++] = s; m = fmaxf(m, s); }

    __shared__ float red[256];
    red[tid] = m; __syncthreads();
    #pragma unroll
    for (int s = 128; s > 0; s >>= 1) {
        if (tid < s) red[tid] = fmaxf(red[tid], red[tid + s]);
        __syncthreads();
    }
    m = red[0]; __syncthreads();

    float sum = 0.f;
    for (int t = 0; t < n; t++) { e[t] = expf(e[t] - m); sum += e[t]; }
    red[tid] = sum; __syncthreads();
    #pragma unroll
    for (int s = 128; s > 0; s >>= 1) {
        if (tid < s) red[tid] += red[tid + s];
        __syncthreads();
    }
    const float inv = 1.0f / red[0];

    int t = 0;
    for (int j = tid; j < L; j += 256) S[j] = e[t++] * inv;
}

// ---------------------------------------------------------------------------
// Kernel 5: O = P @ V, K-extent bounded by causal row tile; writes channels
// [512,1024) of the output.
// ---------------------------------------------------------------------------
__global__ __launch_bounds__(256) void av_kernel(float* __restrict__ out)
{
    const int nt = blockIdx.x, it = blockIdx.y, b = blockIdx.z;
    const float* P = g_s + (size_t)b * TT * TT;
    const float* v = g_v + (size_t)b * TT * CC;
    const int i0 = it * 128, n0 = nt * 128;
    const int Kext = (it + 1) * 128;

    DECL_TILE_STATE();

    const int lrA = tid >> 1, lkA = (tid & 1) * 8;     // A (P): row, k-offset
    const int lrB = tid >> 4, lnB = (tid & 15) * 8;    // B (V): k-row, col

    for (int k0 = 0; k0 < Kext; k0 += 16) {
        const size_t abase = (size_t)(i0 + lrA) * TT + k0 + lkA;
        *(uint4*)&As[lrA][lkA]     = f4tf(*(const float4*)&P[abase]);
        *(uint4*)&As[lrA][lkA + 4] = f4tf(*(const float4*)&P[abase + 4]);
        const size_t bbase = (size_t)(k0 + lrB) * 512 + n0 + lnB;
        *(uint4*)&Bs[lrB][lnB]     = f4tf(*(const float4*)&v[bbase]);
        *(uint4*)&Bs[lrB][lnB + 4] = f4tf(*(const float4*)&v[bbase + 4]);
        __syncthreads();
        MMA_TILE();
        __syncthreads();
    }

    #pragma unroll
    for (int mf = 0; mf < 2; mf++) {
        const int row = i0 + wm * 32 + mf * 16 + gid;
        #pragma unroll
        for (int nf = 0; nf < 8; nf++) {
            const int col = n0 + wn * 64 + nf * 8 + tig * 2;
            const size_t base0 = ((size_t)b * TT + row) * 1024 + 512 + col;
            const size_t base1 = ((size_t)b * TT + row + 8) * 1024 + 512 + col;
            *(float2*)&out[base0] = make_float2(acc[mf][nf][0], acc[mf][nf][1]);
            *(float2*)&out[base1] = make_float2(acc[mf][nf][2], acc[mf][nf][3]);
        }
    }
}

// ---------------------------------------------------------------------------
extern "C" void kernel_launch(void* const* d_in, const int* in_sizes, int n_in,
                              void* d_out, int out_size)
{
    const float* x  = (const float*)d_in[0];
    const float* Wq = (const float*)d_in[1];
    const float* bq = (const float*)d_in[2];
    const float* Wk = (const float*)d_in[3];
    const float* bk = (const float*)d_in[4];
    const float* Wv = (const float*)d_in[5];
    const float* bv = (const float*)d_in[6];
    float* out = (float*)d_out;

    proj_kernel<<<dim3(4, 128, 3), 256>>>(x, Wq, bq, Wk, bk, Wv, bv);

    copy_x_kernel<<<(MTOT * 128) / 256, 256>>>((const float4*)x, (float4*)out);

    score_kernel<<<dim3(16, 16, NB), 256>>>();
    softmax_kernel<<<dim3(TT, NB), 256>>>();
    av_kernel<<<dim3(4, 16, NB), 256>>>(out);
}

// round 8
// speedup vs baseline: 2.9938x; 1.5758x over previous
#include <cuda_runtime.h>

// Problem constants
#define NB   8
#define TT   2048
#define CC   512
#define MTOT (NB*TT)        // 16384
#define NEG_INF __int_as_float(0xff800000)

// Scratch (device globals -- no runtime allocation allowed)
__device__ float g_q[MTOT*CC];
__device__ float g_k[MTOT*CC];
__device__ float g_v[MTOT*CC];
__device__ float g_s[(size_t)NB*TT*TT];

// ---------------------------------------------------------------------------
// mma.sync tf32 (fp32 operands fed raw: HW truncates low mantissa bits)
// ---------------------------------------------------------------------------
__device__ __forceinline__ void mma8(float* c, const unsigned* a, const unsigned* b) {
    asm volatile(
        "mma.sync.aligned.m16n8k8.row.col.f32.tf32.tf32.f32 "
        "{%0,%1,%2,%3}, {%4,%5,%6,%7}, {%8,%9}, {%0,%1,%2,%3};\n"
        : "+f"(c[0]), "+f"(c[1]), "+f"(c[2]), "+f"(c[3])
        : "r"(a[0]), "r"(a[1]), "r"(a[2]), "r"(a[3]), "r"(b[0]), "r"(b[1]));
}

#define CP16(dst, src) \
    asm volatile("cp.async.cg.shared.global [%0], [%1], 16;\n" :: "r"(dst), "l"(src))
#define CPCOMMIT() asm volatile("cp.async.commit_group;\n" ::: "memory")
#define CPWAIT0()  asm volatile("cp.async.wait_group 0;\n" ::: "memory")

// ---------------------------------------------------------------------------
// Tiling: CTA = 128x128, BK = 16, 2-stage cp.async pipeline.
// 8 warps in 4(m) x 2(n); warp tile 32x64 = 2 m-frags x 8 n-frags (m16n8k8).
// A tiles: [2][128][20] fp32 (pitch 20 -> conflict-free frag LDS).
// B tiles: KN layout [2][16][136] (proj/AV) or NK layout [2][128][20] (score).
// ---------------------------------------------------------------------------
#define DECL_TILE_STATE()                                                     \
    const int tid = threadIdx.x;                                              \
    const int wid = tid >> 5, lane = tid & 31;                                \
    const int wm = wid & 3, wn = wid >> 2;                                    \
    const int gid = lane >> 2, tig = lane & 3;                                \
    float acc[2][8][4];                                                       \
    _Pragma("unroll")                                                         \
    for (int mf = 0; mf < 2; mf++)                                            \
        _Pragma("unroll")                                                     \
        for (int nf = 0; nf < 8; nf++)                                        \
            _Pragma("unroll")                                                 \
            for (int q = 0; q < 4; q++) acc[mf][nf][q] = 0.f;

#define BKN(B, k, n) __float_as_uint(B[k][n])
#define BNK(B, k, n) __float_as_uint(B[n][k])

#define COMPUTE_TILE(AB, BB, BIDX)                                            \
    _Pragma("unroll")                                                         \
    for (int ks = 0; ks < 2; ks++) {                                          \
        const int kk = ks * 8;                                                \
        unsigned af[2][4], bf[8][2];                                          \
        _Pragma("unroll")                                                     \
        for (int mf = 0; mf < 2; mf++) {                                      \
            const int r = wm * 32 + mf * 16 + gid;                            \
            af[mf][0] = __float_as_uint(AB[r][kk + tig]);                     \
            af[mf][1] = __float_as_uint(AB[r + 8][kk + tig]);                 \
            af[mf][2] = __float_as_uint(AB[r][kk + tig + 4]);                 \
            af[mf][3] = __float_as_uint(AB[r + 8][kk + tig + 4]);             \
        }                                                                     \
        _Pragma("unroll")                                                     \
        for (int nf = 0; nf < 8; nf++) {                                      \
            const int cb = wn * 64 + nf * 8 + gid;                            \
            bf[nf][0] = BIDX(BB, kk + tig, cb);                               \
            bf[nf][1] = BIDX(BB, kk + tig + 4, cb);                           \
        }                                                                     \
        _Pragma("unroll")                                                     \
        for (int mf = 0; mf < 2; mf++)                                        \
            _Pragma("unroll")                                                 \
            for (int nf = 0; nf < 8; nf++)                                    \
                mma8(acc[mf][nf], af[mf], bf[nf]);                            \
    }

// ---------------------------------------------------------------------------
// Kernel 1: QKV projection.  out[M,512] = X[M,512] @ W[512,512] + bias
// blockIdx.z selects projection (0=Q, 1=K, 2=V).
// ---------------------------------------------------------------------------
__global__ __launch_bounds__(256) void proj_kernel(
    const float* __restrict__ X,
    const float* __restrict__ Wq, const float* __restrict__ bq,
    const float* __restrict__ Wk, const float* __restrict__ bk,
    const float* __restrict__ Wv, const float* __restrict__ bv)
{
    const int which = blockIdx.z;
    const float* W    = (which == 0) ? Wq : (which == 1) ? Wk : Wv;
    const float* bias = (which == 0) ? bq : (which == 1) ? bk : bv;
    float* out        = (which == 0) ? g_q : (which == 1) ? g_k : g_v;

    const int m0 = blockIdx.y * 128;
    const int n0 = blockIdx.x * 128;

    __shared__ float As[2][128][20];
    __shared__ float Bs[2][16][136];

    DECL_TILE_STATE();

    const int ar = tid >> 2, ac = (tid & 3) * 4;      // A: 2 rows (ar, ar+64)
    const int br = tid >> 5, bc = (tid & 31) * 4;     // B: 2 rows (br, br+8)

#define PROJ_ISSUE(s, k0)                                                         \
    do {                                                                          \
        CP16((unsigned)__cvta_generic_to_shared(&As[s][ar][ac]),                  \
             &X[(size_t)(m0 + ar) * 512 + (k0) + ac]);                            \
        CP16((unsigned)__cvta_generic_to_shared(&As[s][ar + 64][ac]),             \
             &X[(size_t)(m0 + ar + 64) * 512 + (k0) + ac]);                       \
        CP16((unsigned)__cvta_generic_to_shared(&Bs[s][br][bc]),                  \
             &W[(size_t)((k0) + br) * 512 + n0 + bc]);                            \
        CP16((unsigned)__cvta_generic_to_shared(&Bs[s][br + 8][bc]),              \
             &W[(size_t)((k0) + br + 8) * 512 + n0 + bc]);                        \
        CPCOMMIT();                                                               \
    } while (0)

    PROJ_ISSUE(0, 0);
    for (int t = 0; t < 32; t++) {
        CPWAIT0();
        __syncthreads();
        if (t + 1 < 32) PROJ_ISSUE((t + 1) & 1, (t + 1) * 16);
        const int cur = t & 1;
        COMPUTE_TILE(As[cur], Bs[cur], BKN);
    }
#undef PROJ_ISSUE

    #pragma unroll
    for (int mf = 0; mf < 2; mf++) {
        const int row = m0 + wm * 32 + mf * 16 + gid;
        #pragma unroll
        for (int nf = 0; nf < 8; nf++) {
            const int col = n0 + wn * 64 + nf * 8 + tig * 2;
            const float b0 = bias[col], b1 = bias[col + 1];
            *(float2*)&out[(size_t)row * 512 + col] =
                make_float2(acc[mf][nf][0] + b0, acc[mf][nf][1] + b1);
            *(float2*)&out[(size_t)(row + 8) * 512 + col] =
                make_float2(acc[mf][nf][2] + b0, acc[mf][nf][3] + b1);
        }
    }
}

// ---------------------------------------------------------------------------
// Kernel 2: copy x into first 512 output channels
// ---------------------------------------------------------------------------
__global__ __launch_bounds__(256) void copy_x_kernel(
    const float4* __restrict__ x4, float4* __restrict__ out4)
{
    const int gid = blockIdx.x * 256 + threadIdx.x;  // MTOT*128 elements
    const int bt = gid >> 7, c4 = gid & 127;
    out4[(size_t)bt * 256 + c4] = x4[gid];
}

// ---------------------------------------------------------------------------
// Kernel 3: scores  S[b,i,j] = (q_i . k_j)/sqrt(512), causal; lower tiles only.
// K tile stays K-major in smem; B frags loaded as Ks[n][k] (conflict-free).
// ---------------------------------------------------------------------------
__global__ __launch_bounds__(256) void score_kernel()
{
    const int jt = blockIdx.x, it = blockIdx.y, b = blockIdx.z;
    if (jt > it) return;

    const float* q = g_q + (size_t)b * TT * CC;
    const float* k = g_k + (size_t)b * TT * CC;
    float*       S = g_s + (size_t)b * TT * TT;
    const int i0 = it * 128, j0 = jt * 128;

    __shared__ float As[2][128][20];
    __shared__ float Ks[2][128][20];

    DECL_TILE_STATE();

    const int ar = tid >> 2, ac = (tid & 3) * 4;

#define SCORE_ISSUE(s, k0)                                                        \
    do {                                                                          \
        CP16((unsigned)__cvta_generic_to_shared(&As[s][ar][ac]),                  \
             &q[(size_t)(i0 + ar) * 512 + (k0) + ac]);                            \
        CP16((unsigned)__cvta_generic_to_shared(&As[s][ar + 64][ac]),             \
             &q[(size_t)(i0 + ar + 64) * 512 + (k0) + ac]);                       \
        CP16((unsigned)__cvta_generic_to_shared(&Ks[s][ar][ac]),                  \
             &k[(size_t)(j0 + ar) * 512 + (k0) + ac]);                            \
        CP16((unsigned)__cvta_generic_to_shared(&Ks[s][ar + 64][ac]),             \
             &k[(size_t)(j0 + ar + 64) * 512 + (k0) + ac]);                       \
        CPCOMMIT();                                                               \
    } while (0)

    SCORE_ISSUE(0, 0);
    for (int t = 0; t < 32; t++) {
        CPWAIT0();
        __syncthreads();
        if (t + 1 < 32) SCORE_ISSUE((t + 1) & 1, (t + 1) * 16);
        const int cur = t & 1;
        COMPUTE_TILE(As[cur], Ks[cur], BNK);
    }
#undef SCORE_ISSUE

    const float scale = 0.044194173824159216f;  // 1/sqrt(512)
    const bool diag = (it == jt);
    #pragma unroll
    for (int mf = 0; mf < 2; mf++) {
        const int row = i0 + wm * 32 + mf * 16 + gid;
        #pragma unroll
        for (int nf = 0; nf < 8; nf++) {
            const int col = j0 + wn * 64 + nf * 8 + tig * 2;
            float2 o0 = make_float2(acc[mf][nf][0] * scale, acc[mf][nf][1] * scale);
            float2 o1 = make_float2(acc[mf][nf][2] * scale, acc[mf][nf][3] * scale);
            if (diag) {
                if (col     > row)     o0.x = NEG_INF;
                if (col + 1 > row)     o0.y = NEG_INF;
                if (col     > row + 8) o1.x = NEG_INF;
                if (col + 1 > row + 8) o1.y = NEG_INF;
            }
            *(float2*)&S[(size_t)row * TT + col]       = o0;
            *(float2*)&S[(size_t)(row + 8) * TT + col] = o1;
        }
    }
}

// ---------------------------------------------------------------------------
// Kernel 4: row softmax (in place); float4 + shfl reductions + __expf.
// ---------------------------------------------------------------------------
__global__ __launch_bounds__(256) void softmax_kernel()
{
    const int i = blockIdx.x, b = blockIdx.y;
    float4* S4 = (float4*)(g_s + (size_t)b * TT * TT + (size_t)i * TT);
    const int L4 = (((i >> 7) + 1) << 7) >> 2;   // ceil(i+1,128)/4, <= 512
    const int tid = threadIdx.x;
    const int wid = tid >> 5, lane = tid & 31;

    float4 e[2];
    int n = 0;
    float m = NEG_INF;
    for (int j = tid; j < L4; j += 256) {
        const float4 s = S4[j];
        e[n++] = s;
        m = fmaxf(m, fmaxf(fmaxf(s.x, s.y), fmaxf(s.z, s.w)));
    }

    __shared__ float wr[8];
    #pragma unroll
    for (int o = 16; o > 0; o >>= 1) m = fmaxf(m, __shfl_xor_sync(~0u, m, o));
    if (lane == 0) wr[wid] = m;
    __syncthreads();
    m = wr[0];
    #pragma unroll
    for (int w = 1; w < 8; w++) m = fmaxf(m, wr[w]);

    float sum = 0.f;
    for (int t = 0; t < n; t++) {
        e[t].x = __expf(e[t].x - m);
        e[t].y = __expf(e[t].y - m);
        e[t].z = __expf(e[t].z - m);
        e[t].w = __expf(e[t].w - m);
        sum += (e[t].x + e[t].y) + (e[t].z + e[t].w);
    }
    __shared__ float ws[8];
    #pragma unroll
    for (int o = 16; o > 0; o >>= 1) sum += __shfl_xor_sync(~0u, sum, o);
    if (lane == 0) ws[wid] = sum;
    __syncthreads();
    sum = ws[0];
    #pragma unroll
    for (int w = 1; w < 8; w++) sum += ws[w];
    const float inv = 1.0f / sum;

    int t = 0;
    for (int j = tid; j < L4; j += 256) {
        float4 o = e[t++];
        o.x *= inv; o.y *= inv; o.z *= inv; o.w *= inv;
        S4[j] = o;
    }
}

// ---------------------------------------------------------------------------
// Kernel 5: O = P @ V, K-extent bounded by causal row tile; writes channels
// [512,1024) of the output.
// ---------------------------------------------------------------------------
__global__ __launch_bounds__(256) void av_kernel(float* __restrict__ out)
{
    const int nt = blockIdx.x, it = blockIdx.y, b = blockIdx.z;
    const float* P = g_s + (size_t)b * TT * TT;
    const float* v = g_v + (size_t)b * TT * CC;
    const int i0 = it * 128, n0 = nt * 128;
    const int nTiles = (it + 1) * 8;   // Kext/16

    __shared__ float As[2][128][20];
    __shared__ float Bs[2][16][136];

    DECL_TILE_STATE();

    const int ar = tid >> 2, ac = (tid & 3) * 4;
    const int br = tid >> 5, bc = (tid & 31) * 4;

#define AV_ISSUE(s, k0)                                                           \
    do {                                                                          \
        CP16((unsigned)__cvta_generic_to_shared(&As[s][ar][ac]),                  \
             &P[(size_t)(i0 + ar) * TT + (k0) + ac]);                             \
        CP16((unsigned)__cvta_generic_to_shared(&As[s][ar + 64][ac]),             \
             &P[(size_t)(i0 + ar + 64) * TT + (k0) + ac]);                        \
        CP16((unsigned)__cvta_generic_to_shared(&Bs[s][br][bc]),                  \
             &v[(size_t)((k0) + br) * 512 + n0 + bc]);                            \
        CP16((unsigned)__cvta_generic_to_shared(&Bs[s][br + 8][bc]),              \
             &v[(size_t)((k0) + br + 8) * 512 + n0 + bc]);                        \
        CPCOMMIT();                                                               \
    } while (0)

    AV_ISSUE(0, 0);
    for (int t = 0; t < nTiles; t++) {
        CPWAIT0();
        __syncthreads();
        if (t + 1 < nTiles) AV_ISSUE((t + 1) & 1, (t + 1) * 16);
        const int cur = t & 1;
        COMPUTE_TILE(As[cur], Bs[cur], BKN);
    }
#undef AV_ISSUE

    #pragma unroll
    for (int mf = 0; mf < 2; mf++) {
        const int row = i0 + wm * 32 + mf * 16 + gid;
        #pragma unroll
        for (int nf = 0; nf < 8; nf++) {
            const int col = n0 + wn * 64 + nf * 8 + tig * 2;
            const size_t base0 = ((size_t)b * TT + row) * 1024 + 512 + col;
            const size_t base1 = ((size_t)b * TT + row + 8) * 1024 + 512 + col;
            *(float2*)&out[base0] = make_float2(acc[mf][nf][0], acc[mf][nf][1]);
            *(float2*)&out[base1] = make_float2(acc[mf][nf][2], acc[mf][nf][3]);
        }
    }
}

// ---------------------------------------------------------------------------
extern "C" void kernel_launch(void* const* d_in, const int* in_sizes, int n_in,
                              void* d_out, int out_size)
{
    const float* x  = (const float*)d_in[0];
    const float* Wq = (const float*)d_in[1];
    const float* bq = (const float*)d_in[2];
    const float* Wk = (const float*)d_in[3];
    const float* bk = (const float*)d_in[4];
    const float* Wv = (const float*)d_in[5];
    const float* bv = (const float*)d_in[6];
    float* out = (float*)d_out;

    proj_kernel<<<dim3(4, 128, 3), 256>>>(x, Wq, bq, Wk, bk, Wv, bv);

    copy_x_kernel<<<(MTOT * 128) / 256, 256>>>((const float4*)x, (float4*)out);

    score_kernel<<<dim3(16, 16, NB), 256>>>();
    softmax_kernel<<<dim3(TT, NB), 256>>>();
    av_kernel<<<dim3(4, 16, NB), 256>>>(out);
}

// round 10
// speedup vs baseline: 3.1409x; 1.0491x over previous
#include <cuda_runtime.h>

// Problem constants
#define NB   8
#define TT   2048
#define CC   512
#define MTOT (NB*TT)        // 16384

// Scratch (device globals -- no runtime allocation allowed)
__device__ float g_q[MTOT*CC];
__device__ float g_k[MTOT*CC];
__device__ float g_v[MTOT*CC];
__device__ float g_s[(size_t)NB*TT*TT];   // holds E = exp(scaled scores)

// ---------------------------------------------------------------------------
// mma.sync tf32 (fp32 operands fed raw: HW truncates low mantissa bits)
// ---------------------------------------------------------------------------
__device__ __forceinline__ void mma8(float* c, const unsigned* a, const unsigned* b) {
    asm volatile(
        "mma.sync.aligned.m16n8k8.row.col.f32.tf32.tf32.f32 "
        "{%0,%1,%2,%3}, {%4,%5,%6,%7}, {%8,%9}, {%0,%1,%2,%3};\n"
        : "+f"(c[0]), "+f"(c[1]), "+f"(c[2]), "+f"(c[3])
        : "r"(a[0]), "r"(a[1]), "r"(a[2]), "r"(a[3]), "r"(b[0]), "r"(b[1]));
}

#define CP16(dst, src) \
    asm volatile("cp.async.cg.shared.global [%0], [%1], 16;\n" :: "r"(dst), "l"(src))
#define CPCOMMIT() asm volatile("cp.async.commit_group;\n" ::: "memory")
#define CPWAIT1()  asm volatile("cp.async.wait_group 1;\n" ::: "memory")

// ---------------------------------------------------------------------------
// Tiling: CTA = 128x128, BK = 16, 3-stage cp.async ring (wait_group 1 keeps
// two tile-loads in flight behind compute; every iteration commits a group --
// possibly empty -- so the wait depth is always correct).
// 8 warps in 4(m) x 2(n); warp tile 32x64 = 2 m-frags x 8 n-frags (m16n8k8).
// A tiles: [3][128][20] fp32 (pitch 20 -> conflict-free frag LDS).
// B tiles: KN [3][16][136] (proj/AV) or NK [3][128][20] (score).
// ---------------------------------------------------------------------------
#define A_STRIDE (128*20)
#define B_STRIDE (16*136)
#define PROJ_SMEM  ((3*A_STRIDE + 3*B_STRIDE) * 4)
#define SCORE_SMEM ((3*A_STRIDE * 2) * 4)
#define AV_SMEM    PROJ_SMEM

extern __shared__ float dynsmem[];

#define DECL_TILE_STATE()                                                     \
    const int tid = threadIdx.x;                                              \
    const int wid = tid >> 5, lane = tid & 31;                                \
    const int wm = wid & 3, wn = wid >> 2;                                    \
    const int gid = lane >> 2, tig = lane & 3;                                \
    float acc[2][8][4];                                                       \
    _Pragma("unroll")                                                         \
    for (int mf = 0; mf < 2; mf++)                                            \
        _Pragma("unroll")                                                     \
        for (int nf = 0; nf < 8; nf++)                                        \
            _Pragma("unroll")                                                 \
            for (int q = 0; q < 4; q++) acc[mf][nf][q] = 0.f;

#define BKN(B, k, n) __float_as_uint(B[k][n])
#define BNK(B, k, n) __float_as_uint(B[n][k])

#define COMPUTE_TILE(AB, BB, BIDX)                                            \
    _Pragma("unroll")                                                         \
    for (int ks = 0; ks < 2; ks++) {                                          \
        const int kk = ks * 8;                                                \
        unsigned af[2][4], bf[8][2];                                          \
        _Pragma("unroll")                                                     \
        for (int mf = 0; mf < 2; mf++) {                                      \
            const int r = wm * 32 + mf * 16 + gid;                            \
            af[mf][0] = __float_as_uint(AB[r][kk + tig]);                     \
            af[mf][1] = __float_as_uint(AB[r + 8][kk + tig]);                 \
            af[mf][2] = __float_as_uint(AB[r][kk + tig + 4]);                 \
            af[mf][3] = __float_as_uint(AB[r + 8][kk + tig + 4]);             \
        }                                                                     \
        _Pragma("unroll")                                                     \
        for (int nf = 0; nf < 8; nf++) {                                      \
            const int cb = wn * 64 + nf * 8 + gid;                            \
            bf[nf][0] = BIDX(BB, kk + tig, cb);                               \
            bf[nf][1] = BIDX(BB, kk + tig + 4, cb);                           \
        }                                                                     \
        _Pragma("unroll")                                                     \
        for (int mf = 0; mf < 2; mf++)                                        \
            _Pragma("unroll")                                                 \
            for (int nf = 0; nf < 8; nf++)                                    \
                mma8(acc[mf][nf], af[mf], bf[nf]);                            \
    }

// AV variant: also accumulates per-row sums of A (=E) into rs[2][2].
#define COMPUTE_TILE_AV(AB, BB)                                               \
    _Pragma("unroll")                                                         \
    for (int ks = 0; ks < 2; ks++) {                                          \
        const int kk = ks * 8;                                                \
        float afv[2][4]; unsigned af[2][4], bf[8][2];                         \
        _Pragma("unroll")                                                     \
        for (int mf = 0; mf < 2; mf++) {                                      \
            const int r = wm * 32 + mf * 16 + gid;                            \
            afv[mf][0] = AB[r][kk + tig];                                     \
            afv[mf][1] = AB[r + 8][kk + tig];                                 \
            afv[mf][2] = AB[r][kk + tig + 4];                                 \
            afv[mf][3] = AB[r + 8][kk + tig + 4];                             \
            rs[mf][0] += afv[mf][0] + afv[mf][2];                             \
            rs[mf][1] += afv[mf][1] + afv[mf][3];                             \
            af[mf][0] = __float_as_uint(afv[mf][0]);                          \
            af[mf][1] = __float_as_uint(afv[mf][1]);                          \
            af[mf][2] = __float_as_uint(afv[mf][2]);                          \
            af[mf][3] = __float_as_uint(afv[mf][3]);                          \
        }                                                                     \
        _Pragma("unroll")                                                     \
        for (int nf = 0; nf < 8; nf++) {                                      \
            const int cb = wn * 64 + nf * 8 + gid;                            \
            bf[nf][0] = __float_as_uint(BB[kk + tig][cb]);                    \
            bf[nf][1] = __float_as_uint(BB[kk + tig + 4][cb]);                \
        }                                                                     \
        _Pragma("unroll")                                                     \
        for (int mf = 0; mf < 2; mf++)                                        \
            _Pragma("unroll")                                                 \
            for (int nf = 0; nf < 8; nf++)                                    \
                mma8(acc[mf][nf], af[mf], bf[nf]);                            \
    }

// ---------------------------------------------------------------------------
// Kernel 1: QKV projection.  out[M,512] = X[M,512] @ W[512,512] + bias
// blockIdx.z selects projection (0=Q, 1=K, 2=V).
// ---------------------------------------------------------------------------
__global__ __launch_bounds__(256) void proj_kernel(
    const float* __restrict__ X,
    const float* __restrict__ Wq, const float* __restrict__ bq,
    const float* __restrict__ Wk, const float* __restrict__ bk,
    const float* __restrict__ Wv, const float* __restrict__ bv)
{
    const int which = blockIdx.z;
    const float* W    = (which == 0) ? Wq : (which == 1) ? Wk : Wv;
    const float* bias = (which == 0) ? bq : (which == 1) ? bk : bv;
    float* out        = (which == 0) ? g_q : (which == 1) ? g_k : g_v;

    const int m0 = blockIdx.y * 128;
    const int n0 = blockIdx.x * 128;

    float (*As)[128][20] = (float(*)[128][20])dynsmem;
    float (*Bs)[16][136] = (float(*)[16][136])(dynsmem + 3 * A_STRIDE);

    DECL_TILE_STATE();

    const int ar = tid >> 2, ac = (tid & 3) * 4;      // A: 2 rows (ar, ar+64)
    const int br = tid >> 5, bc = (tid & 31) * 4;     // B: 2 rows (br, br+8)

#define PROJ_ISSUE(s, k0)                                                         \
    do {                                                                          \
        CP16((unsigned)__cvta_generic_to_shared(&As[s][ar][ac]),                  \
             &X[(size_t)(m0 + ar) * 512 + (k0) + ac]);                            \
        CP16((unsigned)__cvta_generic_to_shared(&As[s][ar + 64][ac]),             \
             &X[(size_t)(m0 + ar + 64) * 512 + (k0) + ac]);                       \
        CP16((unsigned)__cvta_generic_to_shared(&Bs[s][br][bc]),                  \
             &W[(size_t)((k0) + br) * 512 + n0 + bc]);                            \
        CP16((unsigned)__cvta_generic_to_shared(&Bs[s][br + 8][bc]),              \
             &W[(size_t)((k0) + br + 8) * 512 + n0 + bc]);                        \
        CPCOMMIT();                                                               \
    } while (0)

    PROJ_ISSUE(0, 0);
    PROJ_ISSUE(1, 16);
    for (int t = 0; t < 32; t++) {
        CPWAIT1();
        __syncthreads();
        if (t + 2 < 32) { const int s = (t + 2) % 3; PROJ_ISSUE(s, (t + 2) * 16); }
        else CPCOMMIT();
        const int cur = t % 3;
        COMPUTE_TILE(As[cur], Bs[cur], BKN);
    }
#undef PROJ_ISSUE

    #pragma unroll
    for (int mf = 0; mf < 2; mf++) {
        const int row = m0 + wm * 32 + mf * 16 + gid;
        #pragma unroll
        for (int nf = 0; nf < 8; nf++) {
            const int col = n0 + wn * 64 + nf * 8 + tig * 2;
            const float b0 = bias[col], b1 = bias[col + 1];
            *(float2*)&out[(size_t)row * 512 + col] =
                make_float2(acc[mf][nf][0] + b0, acc[mf][nf][1] + b1);
            *(float2*)&out[(size_t)(row + 8) * 512 + col] =
                make_float2(acc[mf][nf][2] + b0, acc[mf][nf][3] + b1);
        }
    }
}

// ---------------------------------------------------------------------------
// Kernel 2: copy x into first 512 output channels
// ---------------------------------------------------------------------------
__global__ __launch_bounds__(256) void copy_x_kernel(
    const float4* __restrict__ x4, float4* __restrict__ out4)
{
    const int gid = blockIdx.x * 256 + threadIdx.x;  // MTOT*128 elements
    const int bt = gid >> 7, c4 = gid & 127;
    out4[(size_t)bt * 256 + c4] = x4[gid];
}

// ---------------------------------------------------------------------------
// Kernel 3: E[b,i,j] = exp((q_i.k_j)/sqrt(512)), causal (0 above diagonal).
// No max-subtraction needed: scaled scores are O(1) bounded, exp cannot
// overflow, and normalization is folded into the AV epilogue.
// Lower-triangle tiles only. K tile stays K-major (B frags read as Ks[n][k]).
// ---------------------------------------------------------------------------
__global__ __launch_bounds__(256) void score_kernel()
{
    const int jt = blockIdx.x, it = blockIdx.y, b = blockIdx.z;
    if (jt > it) return;

    const float* q = g_q + (size_t)b * TT * CC;
    const float* k = g_k + (size_t)b * TT * CC;
    float*       S = g_s + (size_t)b * TT * TT;
    const int i0 = it * 128, j0 = jt * 128;

    float (*As)[128][20] = (float(*)[128][20])dynsmem;
    float (*Ks)[128][20] = (float(*)[128][20])(dynsmem + 3 * A_STRIDE);

    DECL_TILE_STATE();

    const int ar = tid >> 2, ac = (tid & 3) * 4;

#define SCORE_ISSUE(s, k0)                                                        \
    do {                                                                          \
        CP16((unsigned)__cvta_generic_to_shared(&As[s][ar][ac]),                  \
             &q[(size_t)(i0 + ar) * 512 + (k0) + ac]);                            \
        CP16((unsigned)__cvta_generic_to_shared(&As[s][ar + 64][ac]),             \
             &q[(size_t)(i0 + ar + 64) * 512 + (k0) + ac]);                       \
        CP16((unsigned)__cvta_generic_to_shared(&Ks[s][ar][ac]),                  \
             &k[(size_t)(j0 + ar) * 512 + (k0) + ac]);                            \
        CP16((unsigned)__cvta_generic_to_shared(&Ks[s][ar + 64][ac]),             \
             &k[(size_t)(j0 + ar + 64) * 512 + (k0) + ac]);                       \
        CPCOMMIT();                                                              \
    } while (0)

    SCORE_ISSUE(0, 0);
    SCORE_ISSUE(1, 16);
    for (int t = 0; t < 32; t++) {
        CPWAIT1();
        __syncthreads();
        if (t + 2 < 32) { const int s = (t + 2) % 3; SCORE_ISSUE(s, (t + 2) * 16); }
        else CPCOMMIT();
        const int cur = t % 3;
        COMPUTE_TILE(As[cur], Ks[cur], BNK);
    }
#undef SCORE_ISSUE

    const float scale = 0.044194173824159216f;  // 1/sqrt(512)
    const bool diag = (it == jt);
    #pragma unroll
    for (int mf = 0; mf < 2; mf++) {
        const int row = i0 + wm * 32 + mf * 16 + gid;
        #pragma unroll
        for (int nf = 0; nf < 8; nf++) {
            const int col = j0 + wn * 64 + nf * 8 + tig * 2;
            float2 o0 = make_float2(__expf(acc[mf][nf][0] * scale),
                                    __expf(acc[mf][nf][1] * scale));
            float2 o1 = make_float2(__expf(acc[mf][nf][2] * scale),
                                    __expf(acc[mf][nf][3] * scale));
            if (diag) {
                if (col     > row)     o0.x = 0.f;
                if (col + 1 > row)     o0.y = 0.f;
                if (col     > row + 8) o1.x = 0.f;
                if (col + 1 > row + 8) o1.y = 0.f;
            }
            *(float2*)&S[(size_t)row * TT + col]       = o0;
            *(float2*)&S[(size_t)(row + 8) * TT + col] = o1;
        }
    }
}

// ---------------------------------------------------------------------------
// Kernel 4: O = (E @ V) / rowsum(E). Row sums accumulated for free from the
// A-fragments (each warp's nibble covers each k exactly once per row), then
// reduced across the 4 tig lanes with two shfls. Writes channels [512,1024).
// ---------------------------------------------------------------------------
__global__ __launch_bounds__(256) void av_kernel(float* __restrict__ out)
{
    const int nt = blockIdx.x, it = blockIdx.y, b = blockIdx.z;
    const float* P = g_s + (size_t)b * TT * TT;
    const float* v = g_v + (size_t)b * TT * CC;
    const int i0 = it * 128, n0 = nt * 128;
    const int nTiles = (it + 1) * 8;   // Kext/16

    float (*As)[128][20] = (float(*)[128][20])dynsmem;
    float (*Bs)[16][136] = (float(*)[16][136])(dynsmem + 3 * A_STRIDE);

    DECL_TILE_STATE();

    float rs[2][2] = {{0.f, 0.f}, {0.f, 0.f}};

    const int ar = tid >> 2, ac = (tid & 3) * 4;
    const int br = tid >> 5, bc = (tid & 31) * 4;

#define AV_ISSUE(s, k0)                                                           \
    do {                                                                          \
        CP16((unsigned)__cvta_generic_to_shared(&As[s][ar][ac]),                  \
             &P[(size_t)(i0 + ar) * TT + (k0) + ac]);                             \
        CP16((unsigned)__cvta_generic_to_shared(&As[s][ar + 64][ac]),             \
             &P[(size_t)(i0 + ar + 64) * TT + (k0) + ac]);                        \
        CP16((unsigned)__cvta_generic_to_shared(&Bs[s][br][bc]),                  \
             &v[(size_t)((k0) + br) * 512 + n0 + bc]);                            \
        CP16((unsigned)__cvta_generic_to_shared(&Bs[s][br + 8][bc]),              \
             &v[(size_t)((k0) + br + 8) * 512 + n0 + bc]);                        \
        CPCOMMIT();                                                              \
    } while (0)

    AV_ISSUE(0, 0);
    AV_ISSUE(1, 16);
    for (int t = 0; t < nTiles; t++) {
        CPWAIT1();
        __syncthreads();
        if (t + 2 < nTiles) { const int s = (t + 2) % 3; AV_ISSUE(s, (t + 2) * 16); }
        else CPCOMMIT();
        const int cur = t % 3;
        COMPUTE_TILE_AV(As[cur], Bs[cur]);
    }
#undef AV_ISSUE

    // Reduce row sums across the 4 tig lanes of each nibble.
    #pragma unroll
    for (int mf = 0; mf < 2; mf++)
        #pragma unroll
        for (int j = 0; j < 2; j++) {
            rs[mf][j] += __shfl_xor_sync(~0u, rs[mf][j], 1);
            rs[mf][j] += __shfl_xor_sync(~0u, rs[mf][j], 2);
        }

    #pragma unroll
    for (int mf = 0; mf < 2; mf++) {
        const int row = i0 + wm * 32 + mf * 16 + gid;
        const float inv0 = 1.0f / rs[mf][0];
        const float inv1 = 1.0f / rs[mf][1];
        #pragma unroll
        for (int nf = 0; nf < 8; nf++) {
            const int col = n0 + wn * 64 + nf * 8 + tig * 2;
            const size_t base0 = ((size_t)b * TT + row) * 1024 + 512 + col;
            const size_t base1 = ((size_t)b * TT + row + 8) * 1024 + 512 + col;
            *(float2*)&out[base0] = make_float2(acc[mf][nf][0] * inv0,
                                                acc[mf][nf][1] * inv0);
            *(float2*)&out[base1] = make_float2(acc[mf][nf][2] * inv1,
                                                acc[mf][nf][3] * inv1);
        }
    }
}

// ---------------------------------------------------------------------------
extern "C" void kernel_launch(void* const* d_in, const int* in_sizes, int n_in,
                              void* d_out, int out_size)
{
    const float* x  = (const float*)d_in[0];
    const float* Wq = (const float*)d_in[1];
    const float* bq = (const float*)d_in[2];
    const float* Wk = (const float*)d_in[3];
    const float* bk = (const float*)d_in[4];
    const float* Wv = (const float*)d_in[5];
    const float* bv = (const float*)d_in[6];
    float* out = (float*)d_out;

    cudaFuncSetAttribute(proj_kernel,  cudaFuncAttributeMaxDynamicSharedMemorySize, PROJ_SMEM);
    cudaFuncSetAttribute(score_kernel, cudaFuncAttributeMaxDynamicSharedMemorySize, SCORE_SMEM);
    cudaFuncSetAttribute(av_kernel,    cudaFuncAttributeMaxDynamicSharedMemorySize, AV_SMEM);

    proj_kernel<<<dim3(4, 128, 3), 256, PROJ_SMEM>>>(x, Wq, bq, Wk, bk, Wv, bv);

    copy_x_kernel<<<(MTOT * 128) / 256, 256>>>((const float4*)x, (float4*)out);

    score_kernel<<<dim3(16, 16, NB), 256, SCORE_SMEM>>>();
    av_kernel<<<dim3(4, 16, NB), 256, AV_SMEM>>>(out);
}